// round 3
// baseline (speedup 1.0000x reference)
#include <cuda_runtime.h>
#include <cstdint>
#include <math.h>

// ---------------------------------------------------------------------------
// Problem constants
//   x:        [4, 16, 64, 64, 64] f32   (B=4, C=16)
//   weights1: [2, 4] f32
//   weights2: [2, 4] f32
//   out:      [4, 32, 32, 32, 32] f32  (z1 -> ch [0,16) at [0:16]^3,
//                                       z2 -> ch [16,32) at [0:16]^3, rest 0)
// Per point: <Z0> = v^T * Re(U^dag Z0 U) * v, v = real RY product state.
// ---------------------------------------------------------------------------

#define MAXOPS 64

struct Plan {
    int n;
    int type[MAXOPS];   // 0=RX, 1=RY, 2=RZ, 3=CNOT
    int a[MAXOPS];      // rot wire, or cnot control
    int b[MAXOPS];      // cnot target
    int widx[MAXOPS];   // weights flat index l*4+i for rotations
};

// Re(U^dag Z0 U) for weights1 (slot 0) and weights2 (slot 1)
__device__ float g_S[2][16][16];

// ---------------------------------------------------------------------------
// Prelude: simulate circuit on 16 basis columns, form S = Re(U^dag Z0 U).
// grid = 2 blocks (one per weight set), 256 threads.
// ---------------------------------------------------------------------------
__global__ void build_M_kernel(const float* __restrict__ w1,
                               const float* __restrict__ w2,
                               Plan plan) {
    __shared__ float Ur[16][16], Ui[16][16];   // [row k][column b]
    const float* w = (blockIdx.x == 0) ? w1 : w2;
    int t = threadIdx.x;

    if (t < 16) {
        float sr[16], si[16];
        for (int i = 0; i < 16; i++) { sr[i] = (i == t) ? 1.f : 0.f; si[i] = 0.f; }

        for (int o = 0; o < plan.n; o++) {
            int ty = plan.type[o];
            if (ty == 3) {
                // CNOT: flip target where control bit set.
                // qubit q occupies bit (3-q) of flat index b = b0*8+b1*4+b2*2+b3
                int bc = 3 - plan.a[o], bt = 3 - plan.b[o];
                for (int i = 0; i < 16; i++) {
                    if (((i >> bc) & 1) && !((i >> bt) & 1)) {
                        int j2 = i | (1 << bt);
                        float tr = sr[i], ti = si[i];
                        sr[i] = sr[j2]; si[i] = si[j2];
                        sr[j2] = tr;    si[j2] = ti;
                    }
                }
            } else {
                float th = w[plan.widx[o]];
                float c = cosf(0.5f * th), s = sinf(0.5f * th);
                float a00r = c, a00i = 0.f, a01r = 0.f, a01i = 0.f;
                float a10r = 0.f, a10i = 0.f, a11r = c, a11i = 0.f;
                if (ty == 0)      { a01i = -s; a10i = -s; }           // RX
                else if (ty == 1) { a01r = -s; a10r =  s; }           // RY
                else              { a00i = -s; a11i =  s; }           // RZ
                int bit = 3 - plan.a[o];
                int str = 1 << bit;
                for (int i = 0; i < 16; i++) {
                    if (!((i >> bit) & 1)) {
                        int j2 = i + str;
                        float xr = sr[i], xi = si[i], yr = sr[j2], yi = si[j2];
                        sr[i]  = a00r * xr - a00i * xi + a01r * yr - a01i * yi;
                        si[i]  = a00r * xi + a00i * xr + a01r * yi + a01i * yr;
                        sr[j2] = a10r * xr - a10i * xi + a11r * yr - a11i * yi;
                        si[j2] = a10r * xi + a10i * xr + a11r * yi + a11i * yr;
                    }
                }
            }
        }
        for (int k = 0; k < 16; k++) { Ur[k][t] = sr[k]; Ui[k][t] = si[k]; }
    }
    __syncthreads();

    // S[r][c] = sum_k z_k * Re( conj(U[k][r]) * U[k][c] ), z_k = +1 if bit3(k)=0
    int r = t >> 4, c = t & 15;
    float acc = 0.f;
    #pragma unroll
    for (int k = 0; k < 16; k++) {
        float z = (k & 8) ? -1.f : 1.f;
        acc += z * (Ur[k][r] * Ur[k][c] + Ui[k][r] * Ui[k][c]);
    }
    g_S[blockIdx.x][r][c] = acc;
}

// ---------------------------------------------------------------------------
// Zero-fill the output (poisoned by harness; most of it stays zero).
// ---------------------------------------------------------------------------
__global__ void fill_zero_kernel(float4* __restrict__ out, int n4) {
    int i = blockIdx.x * blockDim.x + threadIdx.x;
    if (i < n4) out[i] = make_float4(0.f, 0.f, 0.f, 0.f);
}

// ---------------------------------------------------------------------------
// Main kernel: one thread per patch point, evaluates BOTH circuits
// (they share the 8 corner values of the 2x2x2 input block).
// grid = 1024 blocks (= (b*16+c)*16 + j), block = 256 threads (= k*16 + l)
// ---------------------------------------------------------------------------
__global__ void __launch_bounds__(256)
qconv_kernel(const float* __restrict__ x, float* __restrict__ out) {
    __shared__ float S[2][16][16];
    int t = threadIdx.x;
    {
        int r = t >> 4, c = t & 15;
        S[0][r][c] = g_S[0][r][c];
        S[1][r][c] = g_S[1][r][c];
    }
    __syncthreads();

    int j  = blockIdx.x & 15;
    int bc = blockIdx.x >> 4;      // b*16 + c, 0..63
    int k  = t >> 4;
    int l  = t & 15;

    const float* xb = x + (size_t)bc * 262144 + (size_t)(2 * j) * 4096
                        + (size_t)(2 * k) * 64 + (size_t)(2 * l);

    // 8 corner values g[dj][dk][dl]
    float gv[2][2][2];
    #pragma unroll
    for (int dj = 0; dj < 2; dj++)
        #pragma unroll
        for (int dk = 0; dk < 2; dk++) {
            float2 v2 = *reinterpret_cast<const float2*>(xb + dj * 4096 + dk * 64);
            gv[dj][dk][0] = v2.x;
            gv[dj][dk][1] = v2.y;
        }

    const float PI_F = 3.14159265358979323846f;
    float cc[2][2][2], ss[2][2][2];
    #pragma unroll
    for (int dj = 0; dj < 2; dj++)
        #pragma unroll
        for (int dk = 0; dk < 2; dk++)
            #pragma unroll
            for (int dl = 0; dl < 2; dl++) {
                float a = fminf(PI_F, PI_F * gv[dj][dk][dl]) * 0.5f;
                __sincosf(a, &ss[dj][dk][dl], &cc[dj][dk][dl]);
            }

    auto eval = [&](int which,
                    float c0, float s0, float c1, float s1,
                    float c2, float s2, float c3, float s3) -> float {
        float p01[4] = { c0 * c1, c0 * s1, s0 * c1, s0 * s1 };
        float p23[4] = { c2 * c3, c2 * s3, s2 * c3, s2 * s3 };
        float v[16];
        #pragma unroll
        for (int i = 0; i < 16; i++) v[i] = p01[i >> 2] * p23[i & 3];
        float e = 0.f;
        #pragma unroll
        for (int r = 0; r < 16; r++) {
            float acc = 0.f;
            #pragma unroll
            for (int c = 0; c < 16; c++)
                acc = fmaf(S[which][r][c], v[c], acc);
            e = fmaf(v[r], acc, e);
        }
        return e;
    };

    // circuit 1 angle order: g(0,0,0), g(1,1,0), g(0,1,1), g(1,0,1)
    float e1 = eval(0,
                    cc[0][0][0], ss[0][0][0],
                    cc[1][1][0], ss[1][1][0],
                    cc[0][1][1], ss[0][1][1],
                    cc[1][0][1], ss[1][0][1]);
    // circuit 2 angle order: g(1,1,1), g(0,0,1), g(1,0,0), g(0,1,0)
    float e2 = eval(1,
                    cc[1][1][1], ss[1][1][1],
                    cc[0][0][1], ss[0][0][1],
                    cc[1][0][0], ss[1][0][0],
                    cc[0][1][0], ss[0][1][0]);

    // out[b][ch][j][k][l]; ch-stride 32768, b-stride 1048576
    size_t ob = (size_t)(bc >> 4) * 1048576 + (size_t)(bc & 15) * 32768
              + (size_t)j * 1024 + (size_t)k * 32 + (size_t)l;
    out[ob]          = e1;
    out[ob + 524288] = e2;   // channel offset +16
}

// ---------------------------------------------------------------------------
// Host: exact replication of numpy default_rng(1234) plan generation.
// SeedSequence -> PCG64 (XSL-RR, 128-bit LCG) -> Generator draw sequence.
// ---------------------------------------------------------------------------
typedef unsigned __int128 u128;

struct NpRng {
    u128 state, inc;
    bool has32;
    uint32_t buf32;

    static u128 mult() {
        return ((u128)2549297995355413924ULL << 64) | 4865540595714422341ULL;
    }
    uint64_t next64() {
        state = state * mult() + inc;                 // step, then output
        uint64_t hi = (uint64_t)(state >> 64);
        uint64_t lo = (uint64_t)state;
        unsigned rot = (unsigned)(state >> 122);      // top 6 bits
        uint64_t v = hi ^ lo;
        return (v >> rot) | (v << ((64u - rot) & 63u));
    }
    uint32_t next32() {                               // numpy's buffered pcg64_next32
        if (has32) { has32 = false; return buf32; }
        uint64_t n = next64();
        has32 = true;
        buf32 = (uint32_t)(n >> 32);
        return (uint32_t)n;
    }
    double nextDouble() {                             // next_double bypasses 32-bit buffer
        return (double)(next64() >> 11) * (1.0 / 9007199254740992.0);
    }
    // buffered_bounded_lemire_uint32, inclusive range [0, rng]
    uint32_t lemire32(uint32_t rng) {
        uint32_t rng_excl = rng + 1u;
        uint64_t m = (uint64_t)next32() * (uint64_t)rng_excl;
        uint32_t leftover = (uint32_t)m;
        if (leftover < rng_excl) {
            uint32_t threshold = (uint32_t)((0xFFFFFFFFu - rng) % rng_excl);
            while (leftover < threshold) {
                m = (uint64_t)next32() * (uint64_t)rng_excl;
                leftover = (uint32_t)m;
            }
        }
        return (uint32_t)(m >> 32);
    }
};

static Plan make_plan_host() {
    // --- SeedSequence(1234) ---
    const uint32_t INIT_A = 0x43b0d7e5u, MULT_A = 0x931e8875u;
    const uint32_t INIT_B = 0x8b51f9ddu, MULT_B = 0x58f38dedu;
    const uint32_t MIX_L  = 0xca01f9ddu, MIX_R  = 0x4973f715u;

    uint32_t pool[4];
    uint32_t hc = INIT_A;
    auto hashmix = [&](uint32_t v) -> uint32_t {
        v ^= hc; hc *= MULT_A; v *= hc; v ^= v >> 16; return v;
    };
    // numpy mix(): result = x*MIX_MULT_L - y*MIX_MULT_R; result ^= result >> 16
    auto mixf = [&](uint32_t x, uint32_t y) -> uint32_t {
        uint32_t r = x * MIX_L - y * MIX_R; r ^= r >> 16; return r;
    };
    pool[0] = hashmix(1234u);
    pool[1] = hashmix(0u);
    pool[2] = hashmix(0u);
    pool[3] = hashmix(0u);
    for (int s = 0; s < 4; s++)
        for (int d = 0; d < 4; d++)
            if (s != d) pool[d] = mixf(pool[d], hashmix(pool[s]));

    // generate_state(4, uint64) = 8 uint32 words, little-endian pairs
    uint32_t hb = INIT_B;
    uint32_t st32[8];
    for (int i = 0; i < 8; i++) {
        uint32_t dv = pool[i & 3];
        dv ^= hb; hb *= MULT_B; dv *= hb; dv ^= dv >> 16;
        st32[i] = dv;
    }
    uint64_t s64[4];
    for (int i = 0; i < 4; i++)
        s64[i] = (uint64_t)st32[2 * i] | ((uint64_t)st32[2 * i + 1] << 32);

    // --- PCG64 srandom: initstate = (s64[0]<<64)|s64[1], initseq = (s64[2]<<64)|s64[3]
    NpRng rng;
    u128 initstate = ((u128)s64[0] << 64) | s64[1];
    u128 initseq   = ((u128)s64[2] << 64) | s64[3];
    rng.inc   = (initseq << 1) | 1;
    rng.state = 0;
    rng.state = rng.state * NpRng::mult() + rng.inc;  // step
    rng.state += initstate;
    rng.state = rng.state * NpRng::mult() + rng.inc;  // step
    rng.has32 = false;
    rng.buf32 = 0;

    // --- _make_plan loop ---
    Plan plan;
    plan.n = 0;
    for (int l = 0; l < 2; l++) {
        int i = 0;
        while (i < 4 && plan.n < MAXOPS) {
            if (rng.nextDouble() > 0.3) {
                int g = (int)rng.lemire32(2);   // integers(3): Lemire-32 path
                int w = (int)rng.lemire32(3);   // integers(4)
                plan.type[plan.n] = g;
                plan.a[plan.n]    = w;
                plan.b[plan.n]    = 0;
                plan.widx[plan.n] = l * 4 + i;
                plan.n++;
                i++;
            } else {
                // Generator.choice(4, size=2, replace=False): Floyd + shuffle.
                // Floyd draws: random_bounded_uint64(0, j, 0, 0) -> Lemire-32.
                uint64_t hash_set[4] = { ~0ULL, ~0ULL, ~0ULL, ~0ULL };
                int64_t idx[2];
                for (int jf = 2; jf <= 3; jf++) {
                    uint64_t val = (uint64_t)rng.lemire32((uint32_t)jf);  // [0, jf]
                    uint64_t loc = val & 3;
                    while (hash_set[loc] != ~0ULL && hash_set[loc] != val)
                        loc = (loc + 1) & 3;
                    if (hash_set[loc] == ~0ULL) {
                        hash_set[loc] = val;
                        idx[jf - 2] = (int64_t)val;
                    } else {
                        loc = (uint64_t)jf & 3;
                        while (hash_set[loc] != ~0ULL) loc = (loc + 1) & 3;
                        hash_set[loc] = (uint64_t)jf;
                        idx[jf - 2] = jf;
                    }
                }
                // FIXED: Generator._shuffle_raw draws
                //   j = random_bounded_uint64(&bitgen, 0, i, 0, 0)  (Lemire-32),
                // NOT legacy random_interval. For i=1 Lemire returns the TOP bit
                // of next32 (m = next32*2; m>>32), not the bottom bit.
                uint32_t sh = rng.lemire32(1u);
                int64_t tmp = idx[1]; idx[1] = idx[sh]; idx[sh] = tmp;

                plan.type[plan.n] = 3;
                plan.a[plan.n]    = (int)idx[0];   // control
                plan.b[plan.n]    = (int)idx[1];   // target
                plan.widx[plan.n] = 0;
                plan.n++;
            }
        }
    }
    return plan;
}

// ---------------------------------------------------------------------------
extern "C" void kernel_launch(void* const* d_in, const int* in_sizes, int n_in,
                              void* d_out, int out_size) {
    const float* x  = (const float*)d_in[0];
    const float* w1 = (const float*)d_in[1];
    const float* w2 = (const float*)d_in[2];
    float* out = (float*)d_out;

    Plan plan = make_plan_host();   // deterministic, baked into captured args

    int n4 = out_size / 4;          // 1,048,576 float4s
    fill_zero_kernel<<<(n4 + 255) / 256, 256>>>((float4*)out, n4);
    build_M_kernel<<<2, 256>>>(w1, w2, plan);
    qconv_kernel<<<1024, 256>>>(x, out);
}

// round 5
// speedup vs baseline: 1.3121x; 1.3121x over previous
#include <cuda_runtime.h>
#include <cstdint>
#include <math.h>

// ---------------------------------------------------------------------------
//   x:        [4, 16, 64, 64, 64] f32   (B=4, C=16)
//   weights1/2: [2, 4] f32
//   out:      [4, 32, 32, 32, 32] f32
// Per point: <Z0> = v^T S v, S = Re(U^dag Z0 U), v = ⊗_q (cos a_q, sin a_q).
// Compressed: e = sum_{81 monomials} W[m] * prod_q {c^2, c*s, s^2}_q
// ---------------------------------------------------------------------------

#define MAXOPS 64

struct Plan {
    int n;
    int type[MAXOPS];   // 0=RX, 1=RY, 2=RZ, 3=CNOT
    int a[MAXOPS];      // rot wire, or cnot control
    int b[MAXOPS];      // cnot target
    int widx[MAXOPS];   // weights flat index l*4+i
};

// 81 monomial coefficients per weight set
__device__ float g_W[2][81];

// ---------------------------------------------------------------------------
// Prelude: simulate 16 basis columns, S = Re(U^dag Z0 U), bin into W[81].
// grid = 2 blocks, 256 threads.
// ---------------------------------------------------------------------------
__global__ void build_W_kernel(const float* __restrict__ w1,
                               const float* __restrict__ w2,
                               Plan plan) {
    __shared__ float Ur[16][16], Ui[16][16];   // [row k][column b]
    __shared__ float S[16][16];
    const float* w = (blockIdx.x == 0) ? w1 : w2;
    int t = threadIdx.x;

    if (t < 16) {
        float sr[16], si[16];
        for (int i = 0; i < 16; i++) { sr[i] = (i == t) ? 1.f : 0.f; si[i] = 0.f; }

        for (int o = 0; o < plan.n; o++) {
            int ty = plan.type[o];
            if (ty == 3) {
                int bcb = 3 - plan.a[o], bt = 3 - plan.b[o];
                for (int i = 0; i < 16; i++) {
                    if (((i >> bcb) & 1) && !((i >> bt) & 1)) {
                        int j2 = i | (1 << bt);
                        float tr = sr[i], ti = si[i];
                        sr[i] = sr[j2]; si[i] = si[j2];
                        sr[j2] = tr;    si[j2] = ti;
                    }
                }
            } else {
                float th = w[plan.widx[o]];
                float c = cosf(0.5f * th), s = sinf(0.5f * th);
                float a00r = c, a00i = 0.f, a01r = 0.f, a01i = 0.f;
                float a10r = 0.f, a10i = 0.f, a11r = c, a11i = 0.f;
                if (ty == 0)      { a01i = -s; a10i = -s; }           // RX
                else if (ty == 1) { a01r = -s; a10r =  s; }           // RY
                else              { a00i = -s; a11i =  s; }           // RZ
                int bit = 3 - plan.a[o];
                int str = 1 << bit;
                for (int i = 0; i < 16; i++) {
                    if (!((i >> bit) & 1)) {
                        int j2 = i + str;
                        float xr = sr[i], xi = si[i], yr = sr[j2], yi = si[j2];
                        sr[i]  = a00r * xr - a00i * xi + a01r * yr - a01i * yi;
                        si[i]  = a00r * xi + a00i * xr + a01r * yi + a01i * yr;
                        sr[j2] = a10r * xr - a10i * xi + a11r * yr - a11i * yi;
                        si[j2] = a10r * xi + a10i * xr + a11r * yi + a11i * yr;
                    }
                }
            }
        }
        for (int k = 0; k < 16; k++) { Ur[k][t] = sr[k]; Ui[k][t] = si[k]; }
    }
    __syncthreads();

    {   // S[r][c] = sum_k z_k Re(conj(U[k][r]) U[k][c]), z_k = +- by bit3(k)
        int r = t >> 4, c = t & 15;
        float acc = 0.f;
        #pragma unroll
        for (int k = 0; k < 16; k++) {
            float z = (k & 8) ? -1.f : 1.f;
            acc += z * (Ur[k][r] * Ur[k][c] + Ui[k][r] * Ui[k][c]);
        }
        S[r][c] = acc;
    }
    __syncthreads();

    // Bin: monomial index per qubit m_q = r_q + c_q in {0,1,2} (c^2, c*s, s^2)
    if (t < 81) {
        float acc = 0.f;
        for (int r = 0; r < 16; r++)
            for (int c = 0; c < 16; c++) {
                int m0 = ((r >> 3) & 1) + ((c >> 3) & 1);
                int m1 = ((r >> 2) & 1) + ((c >> 2) & 1);
                int m2 = ((r >> 1) & 1) + ((c >> 1) & 1);
                int m3 = (r & 1) + (c & 1);
                int idx = ((m0 * 3 + m1) * 3 + m2) * 3 + m3;
                if (idx == t) acc += S[r][c];
            }
        g_W[blockIdx.x][t] = acc;
    }
}

// ---------------------------------------------------------------------------
// Fused main kernel.
// grid = 3072 blocks, 256 threads:
//   blocks [0,1024):    compute (b*16+c)*16+j, j<16; write full 32x32 slices
//                       for ch=c and ch=c+16 (zeros outside 16x16 region)
//   blocks [1024,3072): pure-zero slices (all j in [16,32), every channel)
// ---------------------------------------------------------------------------
__device__ __forceinline__ float eval81(const float* __restrict__ W,
                                        float c0, float s0, float c1, float s1,
                                        float c2, float s2, float c3, float s3) {
    float m0[3] = { c0 * c0, c0 * s0, s0 * s0 };
    float m1[3] = { c1 * c1, c1 * s1, s1 * s1 };
    float m2[3] = { c2 * c2, c2 * s2, s2 * s2 };
    float m3[3] = { c3 * c3, c3 * s3, s3 * s3 };
    float M01[9], M23[9];
    #pragma unroll
    for (int a = 0; a < 3; a++)
        #pragma unroll
        for (int b = 0; b < 3; b++) {
            M01[a * 3 + b] = m0[a] * m1[b];
            M23[a * 3 + b] = m2[a] * m3[b];
        }
    float e = 0.f;
    #pragma unroll
    for (int a = 0; a < 9; a++) {
        float tacc = 0.f;
        #pragma unroll
        for (int b = 0; b < 9; b++)
            tacc = fmaf(W[a * 9 + b], M23[b], tacc);
        e = fmaf(M01[a], tacc, e);
    }
    return e;
}

__global__ void __launch_bounds__(256)
qconv_fused_kernel(const float* __restrict__ x, float* __restrict__ out) {
    int t = threadIdx.x;

    if (blockIdx.x >= 1024) {
        // pure-zero slice: (b, ch, j) with j in [16,32)
        int zi = blockIdx.x - 1024;            // 0..2047
        int b  = zi >> 9;
        int ch = (zi >> 4) & 31;
        int j  = 16 + (zi & 15);
        float4* dst = reinterpret_cast<float4*>(
            out + (size_t)b * 1048576 + (size_t)ch * 32768 + (size_t)j * 1024);
        dst[t] = make_float4(0.f, 0.f, 0.f, 0.f);
        return;
    }

    // tile FIRST and 16-byte aligned: the float4 reads from tile require it.
    __shared__ __align__(16) float tile[2][16][16];
    __shared__ float Wsh[2][81];
    if (t < 162) ((float*)Wsh)[t] = ((const float*)g_W)[t];

    int j  = blockIdx.x & 15;
    int bc = blockIdx.x >> 4;      // b*16 + c
    int k  = t >> 4;
    int l  = t & 15;

    const float* xb = x + (size_t)bc * 262144 + (size_t)(2 * j) * 4096
                        + (size_t)(2 * k) * 64 + (size_t)(2 * l);

    float gv[2][2][2];
    #pragma unroll
    for (int dj = 0; dj < 2; dj++)
        #pragma unroll
        for (int dk = 0; dk < 2; dk++) {
            float2 v2 = *reinterpret_cast<const float2*>(xb + dj * 4096 + dk * 64);
            gv[dj][dk][0] = v2.x;
            gv[dj][dk][1] = v2.y;
        }

    const float PI_F = 3.14159265358979323846f;
    float cc[2][2][2], ss[2][2][2];
    #pragma unroll
    for (int dj = 0; dj < 2; dj++)
        #pragma unroll
        for (int dk = 0; dk < 2; dk++)
            #pragma unroll
            for (int dl = 0; dl < 2; dl++) {
                float a = fminf(PI_F, PI_F * gv[dj][dk][dl]) * 0.5f;
                __sincosf(a, &ss[dj][dk][dl], &cc[dj][dk][dl]);
            }

    __syncthreads();   // Wsh ready

    // circuit 1 angle order: g(0,0,0), g(1,1,0), g(0,1,1), g(1,0,1)
    float e1 = eval81(Wsh[0],
                      cc[0][0][0], ss[0][0][0],
                      cc[1][1][0], ss[1][1][0],
                      cc[0][1][1], ss[0][1][1],
                      cc[1][0][1], ss[1][0][1]);
    // circuit 2 angle order: g(1,1,1), g(0,0,1), g(1,0,0), g(0,1,0)
    float e2 = eval81(Wsh[1],
                      cc[1][1][1], ss[1][1][1],
                      cc[0][0][1], ss[0][0][1],
                      cc[1][0][0], ss[1][0][0],
                      cc[0][1][0], ss[0][1][0]);

    tile[0][k][l] = e1;
    tile[1][k][l] = e2;
    __syncthreads();

    // Write both channel slices (32x32 each), zeros outside computed 16x16.
    int b = bc >> 4, c = bc & 15;
    int k2 = t >> 3;          // output row 0..31
    int q  = t & 7;           // float4 quad 0..7 (cols 4q..4q+3)
    const float4 z4 = make_float4(0.f, 0.f, 0.f, 0.f);
    #pragma unroll
    for (int s = 0; s < 2; s++) {
        float4 v = (k2 < 16 && q < 4)
                 ? reinterpret_cast<const float4*>(tile[s][k2])[q] : z4;
        float4* dst = reinterpret_cast<float4*>(
            out + (size_t)b * 1048576 + (size_t)(c + 16 * s) * 32768
                + (size_t)j * 1024);
        dst[t] = v;
    }
}

// ---------------------------------------------------------------------------
// Host: exact numpy default_rng(1234) plan generation (verified R3).
// ---------------------------------------------------------------------------
typedef unsigned __int128 u128;

struct NpRng {
    u128 state, inc;
    bool has32;
    uint32_t buf32;

    static u128 mult() {
        return ((u128)2549297995355413924ULL << 64) | 4865540595714422341ULL;
    }
    uint64_t next64() {
        state = state * mult() + inc;
        uint64_t hi = (uint64_t)(state >> 64);
        uint64_t lo = (uint64_t)state;
        unsigned rot = (unsigned)(state >> 122);
        uint64_t v = hi ^ lo;
        return (v >> rot) | (v << ((64u - rot) & 63u));
    }
    uint32_t next32() {
        if (has32) { has32 = false; return buf32; }
        uint64_t n = next64();
        has32 = true;
        buf32 = (uint32_t)(n >> 32);
        return (uint32_t)n;
    }
    double nextDouble() {
        return (double)(next64() >> 11) * (1.0 / 9007199254740992.0);
    }
    uint32_t lemire32(uint32_t rng) {
        uint32_t rng_excl = rng + 1u;
        uint64_t m = (uint64_t)next32() * (uint64_t)rng_excl;
        uint32_t leftover = (uint32_t)m;
        if (leftover < rng_excl) {
            uint32_t threshold = (uint32_t)((0xFFFFFFFFu - rng) % rng_excl);
            while (leftover < threshold) {
                m = (uint64_t)next32() * (uint64_t)rng_excl;
                leftover = (uint32_t)m;
            }
        }
        return (uint32_t)(m >> 32);
    }
};

static Plan make_plan_host() {
    const uint32_t INIT_A = 0x43b0d7e5u, MULT_A = 0x931e8875u;
    const uint32_t INIT_B = 0x8b51f9ddu, MULT_B = 0x58f38dedu;
    const uint32_t MIX_L  = 0xca01f9ddu, MIX_R  = 0x4973f715u;

    uint32_t pool[4];
    uint32_t hc = INIT_A;
    auto hashmix = [&](uint32_t v) -> uint32_t {
        v ^= hc; hc *= MULT_A; v *= hc; v ^= v >> 16; return v;
    };
    auto mixf = [&](uint32_t x, uint32_t y) -> uint32_t {
        uint32_t r = x * MIX_L - y * MIX_R; r ^= r >> 16; return r;
    };
    pool[0] = hashmix(1234u);
    pool[1] = hashmix(0u);
    pool[2] = hashmix(0u);
    pool[3] = hashmix(0u);
    for (int s = 0; s < 4; s++)
        for (int d = 0; d < 4; d++)
            if (s != d) pool[d] = mixf(pool[d], hashmix(pool[s]));

    uint32_t hb = INIT_B;
    uint32_t st32[8];
    for (int i = 0; i < 8; i++) {
        uint32_t dv = pool[i & 3];
        dv ^= hb; hb *= MULT_B; dv *= hb; dv ^= dv >> 16;
        st32[i] = dv;
    }
    uint64_t s64[4];
    for (int i = 0; i < 4; i++)
        s64[i] = (uint64_t)st32[2 * i] | ((uint64_t)st32[2 * i + 1] << 32);

    NpRng rng;
    u128 initstate = ((u128)s64[0] << 64) | s64[1];
    u128 initseq   = ((u128)s64[2] << 64) | s64[3];
    rng.inc   = (initseq << 1) | 1;
    rng.state = 0;
    rng.state = rng.state * NpRng::mult() + rng.inc;
    rng.state += initstate;
    rng.state = rng.state * NpRng::mult() + rng.inc;
    rng.has32 = false;
    rng.buf32 = 0;

    Plan plan;
    plan.n = 0;
    for (int l = 0; l < 2; l++) {
        int i = 0;
        while (i < 4 && plan.n < MAXOPS) {
            if (rng.nextDouble() > 0.3) {
                int g = (int)rng.lemire32(2);
                int w = (int)rng.lemire32(3);
                plan.type[plan.n] = g;
                plan.a[plan.n]    = w;
                plan.b[plan.n]    = 0;
                plan.widx[plan.n] = l * 4 + i;
                plan.n++;
                i++;
            } else {
                uint64_t hash_set[4] = { ~0ULL, ~0ULL, ~0ULL, ~0ULL };
                int64_t idx[2];
                for (int jf = 2; jf <= 3; jf++) {
                    uint64_t val = (uint64_t)rng.lemire32((uint32_t)jf);
                    uint64_t loc = val & 3;
                    while (hash_set[loc] != ~0ULL && hash_set[loc] != val)
                        loc = (loc + 1) & 3;
                    if (hash_set[loc] == ~0ULL) {
                        hash_set[loc] = val;
                        idx[jf - 2] = (int64_t)val;
                    } else {
                        loc = (uint64_t)jf & 3;
                        while (hash_set[loc] != ~0ULL) loc = (loc + 1) & 3;
                        hash_set[loc] = (uint64_t)jf;
                        idx[jf - 2] = jf;
                    }
                }
                uint32_t sh = rng.lemire32(1u);   // Lemire-32 (top bit)
                int64_t tmp = idx[1]; idx[1] = idx[sh]; idx[sh] = tmp;

                plan.type[plan.n] = 3;
                plan.a[plan.n]    = (int)idx[0];
                plan.b[plan.n]    = (int)idx[1];
                plan.widx[plan.n] = 0;
                plan.n++;
            }
        }
    }
    return plan;
}

// ---------------------------------------------------------------------------
extern "C" void kernel_launch(void* const* d_in, const int* in_sizes, int n_in,
                              void* d_out, int out_size) {
    const float* x  = (const float*)d_in[0];
    const float* w1 = (const float*)d_in[1];
    const float* w2 = (const float*)d_in[2];
    float* out = (float*)d_out;

    Plan plan = make_plan_host();

    build_W_kernel<<<2, 256>>>(w1, w2, plan);
    qconv_fused_kernel<<<3072, 256>>>(x, out);
}

// round 7
// speedup vs baseline: 1.8211x; 1.3879x over previous
#include <cuda_runtime.h>
#include <cstdint>
#include <math.h>

// ---------------------------------------------------------------------------
//   x:        [4, 16, 64, 64, 64] f32   (B=4, C=16)
//   weights1/2: [2, 4] f32
//   out:      [4, 32, 32, 32, 32] f32
// Per point: <Z0> = v^T S v, S = Re(U^dag Z0 U), v = ⊗_q (cos a_q, sin a_q).
// Compressed to 81 monomial coeffs, expressed in double-angle basis
// (1, cos 2a_q, sin 2a_q);  2a = min(pi, pi*y).
// ---------------------------------------------------------------------------

#define MAXOPS 64

struct Plan {
    int n;
    int type[MAXOPS];   // 0=RX, 1=RY, 2=RZ, 3=CNOT
    int a[MAXOPS];      // rot wire, or cnot control
    int b[MAXOPS];      // cnot target
    int widx[MAXOPS];   // weights flat index l*4+i
};

// 81 coefficients per weight set, double-angle basis
__device__ float g_W[2][81];

// ---------------------------------------------------------------------------
// Prelude: fully parallel circuit sim. Thread (col, amp) keeps one complex
// amplitude of basis-column col in registers; gates use warp shuffles
// (pairs amp, amp^str live in the same 16-lane half-warp).
// grid = 2 blocks (one per weight set), 256 threads.
// ---------------------------------------------------------------------------
__global__ void build_W_kernel(const float* __restrict__ w1,
                               const float* __restrict__ w2,
                               Plan plan) {
    __shared__ float Ur[16][16], Ui[16][16];   // [amp k][column b]
    __shared__ float WA[81], WB[81];
    const float* w = (blockIdx.x == 0) ? w1 : w2;
    int t    = threadIdx.x;
    int col  = t >> 4;
    int amp  = t & 15;
    int lane = t & 31;

    float sr = (amp == col) ? 1.f : 0.f;
    float si = 0.f;

    for (int o = 0; o < plan.n; o++) {
        int ty = plan.type[o];
        if (ty == 3) {
            // CNOT gather: new[i] = old[i ^ (bit_bc(i) ? str_t : 0)]
            int bcb = 3 - plan.a[o], btb = 3 - plan.b[o];
            int src_amp  = amp ^ ((((amp >> bcb) & 1) ? 1 : 0) << btb);
            int src_lane = (lane & 16) | src_amp;
            sr = __shfl_sync(0xFFFFFFFFu, sr, src_lane);
            si = __shfl_sync(0xFFFFFFFFu, si, src_lane);
        } else {
            float th = w[plan.widx[o]];
            float c = cosf(0.5f * th), s = sinf(0.5f * th);
            float a00r = c, a00i = 0.f, a01r = 0.f, a01i = 0.f;
            float a10r = 0.f, a10i = 0.f, a11r = c, a11i = 0.f;
            if (ty == 0)      { a01i = -s; a10i = -s; }           // RX
            else if (ty == 1) { a01r = -s; a10r =  s; }           // RY
            else              { a00i = -s; a11i =  s; }           // RZ
            int bitp = 3 - plan.a[o];
            int str  = 1 << bitp;
            float pr = __shfl_xor_sync(0xFFFFFFFFu, sr, str);
            float pi = __shfl_xor_sync(0xFFFFFFFFu, si, str);
            int bit = (amp >> bitp) & 1;
            float xr = bit ? pr : sr, xi = bit ? pi : si;
            float yr = bit ? sr : pr, yi = bit ? si : pi;
            float r0r = bit ? a10r : a00r, r0i = bit ? a10i : a00i;
            float r1r = bit ? a11r : a01r, r1i = bit ? a11i : a01i;
            sr = r0r * xr - r0i * xi + r1r * yr - r1i * yi;
            si = r0r * xi + r0i * xr + r1r * yi + r1i * yr;
        }
    }
    Ur[amp][col] = sr;
    Ui[amp][col] = si;
    if (t < 81) WA[t] = 0.f;
    __syncthreads();

    // S[r][c] = sum_k z_k Re(conj(U[k][r]) U[k][c]), z_k by bit3(k);
    // bin into 81 monomials (m_q = r_q + c_q) via shared atomics.
    {
        int r = t >> 4, c = t & 15;
        float acc = 0.f;
        #pragma unroll
        for (int k = 0; k < 16; k++) {
            float z = (k & 8) ? -1.f : 1.f;
            acc += z * (Ur[k][r] * Ur[k][c] + Ui[k][r] * Ui[k][c]);
        }
        int m0 = ((r >> 3) & 1) + ((c >> 3) & 1);
        int m1 = ((r >> 2) & 1) + ((c >> 2) & 1);
        int m2 = ((r >> 1) & 1) + ((c >> 1) & 1);
        int m3 = (r & 1) + (c & 1);
        int idx = ((m0 * 3 + m1) * 3 + m2) * 3 + m3;
        atomicAdd(&WA[idx], acc);
    }

    // Basis change per axis: [c^2, cs, s^2] -> [1, cos2a, sin2a]:
    //   out0 = .5*(in0+in2), out1 = .5*(in0-in2), out2 = .5*in1
    #define XFORM(SRC, DST, S)                                            \
        __syncthreads();                                                  \
        if (t < 81) {                                                     \
            int n = (t / (S)) % 3;                                        \
            int base = t - n * (S);                                       \
            float i0 = SRC[base], i1 = SRC[base + (S)], i2 = SRC[base + 2 * (S)]; \
            DST[t] = (n == 0) ? 0.5f * (i0 + i2)                          \
                   : (n == 1) ? 0.5f * (i0 - i2) : 0.5f * i1;             \
        }
    XFORM(WA, WB, 27)
    XFORM(WB, WA, 9)
    XFORM(WA, WB, 3)
    XFORM(WB, WA, 1)
    #undef XFORM

    __syncthreads();
    if (t < 81) g_W[blockIdx.x][t] = WA[t];
}

// ---------------------------------------------------------------------------
// Fused main kernel; double-angle eval.
// grid = 3072 blocks, 256 threads.
// ---------------------------------------------------------------------------
__device__ __forceinline__ float eval81(const float* __restrict__ W,
                                        float C0, float S0, float C1, float S1,
                                        float C2, float S2, float C3, float S3) {
    float M01[9] = { 1.f, C1, S1,
                     C0,  C0 * C1, C0 * S1,
                     S0,  S0 * C1, S0 * S1 };
    float M23[9] = { 1.f, C3, S3,
                     C2,  C2 * C3, C2 * S3,
                     S2,  S2 * C3, S2 * S3 };
    float e = 0.f;
    #pragma unroll
    for (int a = 0; a < 9; a++) {
        float tacc = 0.f;
        #pragma unroll
        for (int b = 0; b < 9; b++)
            tacc = fmaf(W[a * 9 + b], M23[b], tacc);
        e = fmaf(M01[a], tacc, e);
    }
    return e;
}

__global__ void __launch_bounds__(256)
qconv_fused_kernel(const float* __restrict__ x, float* __restrict__ out) {
    int t = threadIdx.x;

    if (blockIdx.x >= 1024) {
        // pure-zero slice: (b, ch, j) with j in [16,32)
        int zi = blockIdx.x - 1024;            // 0..2047
        int b  = zi >> 9;
        int ch = (zi >> 4) & 31;
        int j  = 16 + (zi & 15);
        float4* dst = reinterpret_cast<float4*>(
            out + (size_t)b * 1048576 + (size_t)ch * 32768 + (size_t)j * 1024);
        dst[t] = make_float4(0.f, 0.f, 0.f, 0.f);
        return;
    }

    __shared__ __align__(16) float tile[2][16][16];
    __shared__ float Wsh[2][81];
    if (t < 162) ((float*)Wsh)[t] = ((const float*)g_W)[t];

    int j  = blockIdx.x & 15;
    int bc = blockIdx.x >> 4;      // b*16 + c
    int k  = t >> 4;
    int l  = t & 15;

    const float* xb = x + (size_t)bc * 262144 + (size_t)(2 * j) * 4096
                        + (size_t)(2 * k) * 64 + (size_t)(2 * l);

    float gv[2][2][2];
    #pragma unroll
    for (int dj = 0; dj < 2; dj++)
        #pragma unroll
        for (int dk = 0; dk < 2; dk++) {
            float2 v2 = *reinterpret_cast<const float2*>(xb + dj * 4096 + dk * 64);
            gv[dj][dk][0] = v2.x;
            gv[dj][dk][1] = v2.y;
        }

    // Double angle: a = min(pi, pi*y)/2  =>  2a = min(pi, pi*y).
    // (R6 bug was min(2pi, 2pi*y) = 4a.)
    const float PI_F = 3.14159265358979323846f;
    float CC[2][2][2], SS[2][2][2];
    #pragma unroll
    for (int dj = 0; dj < 2; dj++)
        #pragma unroll
        for (int dk = 0; dk < 2; dk++)
            #pragma unroll
            for (int dl = 0; dl < 2; dl++) {
                float th2 = fminf(PI_F, PI_F * gv[dj][dk][dl]);
                __sincosf(th2, &SS[dj][dk][dl], &CC[dj][dk][dl]);
            }

    __syncthreads();   // Wsh ready

    // circuit 1 angle order: g(0,0,0), g(1,1,0), g(0,1,1), g(1,0,1)
    float e1 = eval81(Wsh[0],
                      CC[0][0][0], SS[0][0][0],
                      CC[1][1][0], SS[1][1][0],
                      CC[0][1][1], SS[0][1][1],
                      CC[1][0][1], SS[1][0][1]);
    // circuit 2 angle order: g(1,1,1), g(0,0,1), g(1,0,0), g(0,1,0)
    float e2 = eval81(Wsh[1],
                      CC[1][1][1], SS[1][1][1],
                      CC[0][0][1], SS[0][0][1],
                      CC[1][0][0], SS[1][0][0],
                      CC[0][1][0], SS[0][1][0]);

    tile[0][k][l] = e1;
    tile[1][k][l] = e2;
    __syncthreads();

    // Write both channel slices (32x32 each), zeros outside computed 16x16.
    int b = bc >> 4, c = bc & 15;
    int k2 = t >> 3;          // output row 0..31
    int q  = t & 7;           // float4 quad 0..7
    const float4 z4 = make_float4(0.f, 0.f, 0.f, 0.f);
    #pragma unroll
    for (int s = 0; s < 2; s++) {
        float4 v = (k2 < 16 && q < 4)
                 ? reinterpret_cast<const float4*>(tile[s][k2])[q] : z4;
        float4* dst = reinterpret_cast<float4*>(
            out + (size_t)b * 1048576 + (size_t)(c + 16 * s) * 32768
                + (size_t)j * 1024);
        dst[t] = v;
    }
}

// ---------------------------------------------------------------------------
// Host: exact numpy default_rng(1234) plan generation (verified R3).
// ---------------------------------------------------------------------------
typedef unsigned __int128 u128;

struct NpRng {
    u128 state, inc;
    bool has32;
    uint32_t buf32;

    static u128 mult() {
        return ((u128)2549297995355413924ULL << 64) | 4865540595714422341ULL;
    }
    uint64_t next64() {
        state = state * mult() + inc;
        uint64_t hi = (uint64_t)(state >> 64);
        uint64_t lo = (uint64_t)state;
        unsigned rot = (unsigned)(state >> 122);
        uint64_t v = hi ^ lo;
        return (v >> rot) | (v << ((64u - rot) & 63u));
    }
    uint32_t next32() {
        if (has32) { has32 = false; return buf32; }
        uint64_t n = next64();
        has32 = true;
        buf32 = (uint32_t)(n >> 32);
        return (uint32_t)n;
    }
    double nextDouble() {
        return (double)(next64() >> 11) * (1.0 / 9007199254740992.0);
    }
    uint32_t lemire32(uint32_t rng) {
        uint32_t rng_excl = rng + 1u;
        uint64_t m = (uint64_t)next32() * (uint64_t)rng_excl;
        uint32_t leftover = (uint32_t)m;
        if (leftover < rng_excl) {
            uint32_t threshold = (uint32_t)((0xFFFFFFFFu - rng) % rng_excl);
            while (leftover < threshold) {
                m = (uint64_t)next32() * (uint64_t)rng_excl;
                leftover = (uint32_t)m;
            }
        }
        return (uint32_t)(m >> 32);
    }
};

static Plan make_plan_host() {
    const uint32_t INIT_A = 0x43b0d7e5u, MULT_A = 0x931e8875u;
    const uint32_t INIT_B = 0x8b51f9ddu, MULT_B = 0x58f38dedu;
    const uint32_t MIX_L  = 0xca01f9ddu, MIX_R  = 0x4973f715u;

    uint32_t pool[4];
    uint32_t hc = INIT_A;
    auto hashmix = [&](uint32_t v) -> uint32_t {
        v ^= hc; hc *= MULT_A; v *= hc; v ^= v >> 16; return v;
    };
    auto mixf = [&](uint32_t x, uint32_t y) -> uint32_t {
        uint32_t r = x * MIX_L - y * MIX_R; r ^= r >> 16; return r;
    };
    pool[0] = hashmix(1234u);
    pool[1] = hashmix(0u);
    pool[2] = hashmix(0u);
    pool[3] = hashmix(0u);
    for (int s = 0; s < 4; s++)
        for (int d = 0; d < 4; d++)
            if (s != d) pool[d] = mixf(pool[d], hashmix(pool[s]));

    uint32_t hb = INIT_B;
    uint32_t st32[8];
    for (int i = 0; i < 8; i++) {
        uint32_t dv = pool[i & 3];
        dv ^= hb; hb *= MULT_B; dv *= hb; dv ^= dv >> 16;
        st32[i] = dv;
    }
    uint64_t s64[4];
    for (int i = 0; i < 4; i++)
        s64[i] = (uint64_t)st32[2 * i] | ((uint64_t)st32[2 * i + 1] << 32);

    NpRng rng;
    u128 initstate = ((u128)s64[0] << 64) | s64[1];
    u128 initseq   = ((u128)s64[2] << 64) | s64[3];
    rng.inc   = (initseq << 1) | 1;
    rng.state = 0;
    rng.state = rng.state * NpRng::mult() + rng.inc;
    rng.state += initstate;
    rng.state = rng.state * NpRng::mult() + rng.inc;
    rng.has32 = false;
    rng.buf32 = 0;

    Plan plan;
    plan.n = 0;
    for (int l = 0; l < 2; l++) {
        int i = 0;
        while (i < 4 && plan.n < MAXOPS) {
            if (rng.nextDouble() > 0.3) {
                int g = (int)rng.lemire32(2);
                int w = (int)rng.lemire32(3);
                plan.type[plan.n] = g;
                plan.a[plan.n]    = w;
                plan.b[plan.n]    = 0;
                plan.widx[plan.n] = l * 4 + i;
                plan.n++;
                i++;
            } else {
                uint64_t hash_set[4] = { ~0ULL, ~0ULL, ~0ULL, ~0ULL };
                int64_t idx[2];
                for (int jf = 2; jf <= 3; jf++) {
                    uint64_t val = (uint64_t)rng.lemire32((uint32_t)jf);
                    uint64_t loc = val & 3;
                    while (hash_set[loc] != ~0ULL && hash_set[loc] != val)
                        loc = (loc + 1) & 3;
                    if (hash_set[loc] == ~0ULL) {
                        hash_set[loc] = val;
                        idx[jf - 2] = (int64_t)val;
                    } else {
                        loc = (uint64_t)jf & 3;
                        while (hash_set[loc] != ~0ULL) loc = (loc + 1) & 3;
                        hash_set[loc] = (uint64_t)jf;
                        idx[jf - 2] = jf;
                    }
                }
                uint32_t sh = rng.lemire32(1u);   // Lemire-32 (top bit)
                int64_t tmp = idx[1]; idx[1] = idx[sh]; idx[sh] = tmp;

                plan.type[plan.n] = 3;
                plan.a[plan.n]    = (int)idx[0];
                plan.b[plan.n]    = (int)idx[1];
                plan.widx[plan.n] = 0;
                plan.n++;
            }
        }
    }
    return plan;
}

// ---------------------------------------------------------------------------
extern "C" void kernel_launch(void* const* d_in, const int* in_sizes, int n_in,
                              void* d_out, int out_size) {
    const float* x  = (const float*)d_in[0];
    const float* w1 = (const float*)d_in[1];
    const float* w2 = (const float*)d_in[2];
    float* out = (float*)d_out;

    Plan plan = make_plan_host();

    build_W_kernel<<<2, 256>>>(w1, w2, plan);
    qconv_fused_kernel<<<3072, 256>>>(x, out);
}